// round 15
// baseline (speedup 1.0000x reference)
#include <cuda_runtime.h>
#include <cuda_fp16.h>
#include <cstdint>

#define NB   2
#define NT   2048
#define ND   2048
#define NHQ  32
#define NHKV 8
#define NDH  64
#define NTOK (NB*NT)      // 4096
#define NDKV (NHKV*NDH)   // 512

// fp16 scratch (device globals: allocation-free per harness rules)
__device__ __half g_Qh[(size_t)NTOK * ND];     // 16 MB
__device__ __half g_Kh[(size_t)NTOK * NDKV];   // 4 MB
__device__ __half g_Vh[(size_t)NTOK * NDKV];   // 4 MB
__device__ __half g_Ah[(size_t)NTOK * ND];     // 16 MB
__device__ __half g_Xh[(size_t)NTOK * ND];     // 16 MB
__device__ __half g_WqT[(size_t)ND * ND];      // 8 MB  [N][K]
__device__ __half g_WkT[(size_t)NDKV * ND];    // 2 MB
__device__ __half g_WvT[(size_t)NDKV * ND];    // 2 MB
__device__ __half g_WoT[(size_t)ND * ND];      // 8 MB

// ---------------------------------------------------------------------------
__device__ __forceinline__ void mma_f16(float* c, uint32_t a0, uint32_t a1,
                                        uint32_t a2, uint32_t a3,
                                        uint32_t b0, uint32_t b1) {
    asm volatile(
        "mma.sync.aligned.m16n8k16.row.col.f32.f16.f16.f32 "
        "{%0,%1,%2,%3}, {%4,%5,%6,%7}, {%8,%9}, {%0,%1,%2,%3};"
        : "+f"(c[0]), "+f"(c[1]), "+f"(c[2]), "+f"(c[3])
        : "r"(a0), "r"(a1), "r"(a2), "r"(a3), "r"(b0), "r"(b1));
}

__device__ __forceinline__ void cp_async16(void* smem_ptr, const void* gptr) {
    unsigned saddr = (unsigned)__cvta_generic_to_shared(smem_ptr);
    asm volatile("cp.async.cg.shared.global [%0], [%1], 16;\n"
                 :: "r"(saddr), "l"(gptr));
}

__device__ __forceinline__ uint32_t pack_half2(float lo, float hi) {
    uint32_t r;
    asm("cvt.rn.f16x2.f32 %0, %2, %1;" : "=r"(r) : "f"(lo), "f"(hi));
    return r;
}

// ---------------------------------------------------------------------------
// prep kernels
// ---------------------------------------------------------------------------
__global__ __launch_bounds__(256) void cvt_half(
    const float* __restrict__ in, __half* __restrict__ out, int n4)
{
    int i = blockIdx.x * blockDim.x + threadIdx.x;
    if (i < n4) {
        float4 v = ((const float4*)in)[i];
        __half2* o = (__half2*)(out + 4 * (size_t)i);
        o[0] = __floats2half2_rn(v.x, v.y);
        o[1] = __floats2half2_rn(v.z, v.w);
    }
}

// fused transpose of all 4 weights: z selects matrix. fp32 [R][C] -> fp16 [C][R]
__global__ __launch_bounds__(256) void transpose4(
    const float* __restrict__ Wq, const float* __restrict__ Wk,
    const float* __restrict__ Wv, const float* __restrict__ Wo,
    __half* __restrict__ WqT, __half* __restrict__ WkT,
    __half* __restrict__ WvT, __half* __restrict__ WoT)
{
    const int z = blockIdx.z;
    const float* in;
    __half* out;
    int C;
    if (z == 0)      { in = Wq; out = WqT; C = ND; }
    else if (z == 1) { in = Wk; out = WkT; C = NDKV; }
    else if (z == 2) { in = Wv; out = WvT; C = NDKV; }
    else             { in = Wo; out = WoT; C = ND; }
    const int c0 = blockIdx.x * 32;
    if (c0 >= C) return;
    const int R = ND;
    const int r0 = blockIdx.y * 32;

    __shared__ float t[32][33];
    const int tx = threadIdx.x & 31;
    const int ty = threadIdx.x >> 5;
    #pragma unroll
    for (int i = 0; i < 32; i += 8)
        t[ty + i][tx] = in[(size_t)(r0 + ty + i) * C + c0 + tx];
    __syncthreads();
    #pragma unroll
    for (int i = 0; i < 32; i += 8)
        out[(size_t)(c0 + ty + i) * R + r0 + tx] = __float2half_rn(t[tx][ty + i]);
}

// ---------------------------------------------------------------------------
// fp16 GEMM: block 128x128, BK=64 (halved barrier count), warp tile 32x64,
// 3-stage cp.async ring, 2 CTAs/SM. A fp16 [M][K], BT fp16 [N][K].
// Smem pitch 36 u32/row (32 used + 4 pad) -> frag LDS conflict-free
// (bank = 4g + 8kc + t), STS hits each bank exactly 4x per warp.
// ---------------------------------------------------------------------------
#define GP     36                       // u32 pitch per row
#define GS_A   (128 * GP)               // 4608 u32
#define GS_B   (128 * GP)               // 4608 u32
#define GSTG   (GS_A + GS_B)            // 9216 u32
#define G_SMEM (3 * GSTG * (int)sizeof(uint32_t))   // 110592 B

__device__ __forceinline__ void gemm_core_h(
    const __half* __restrict__ A, const __half* __restrict__ BT,
    void* __restrict__ C, bool half_out, int N, int K, int bx, int by,
    uint32_t* gsm)
{
    const int tid  = threadIdx.x;
    const int warp = tid >> 5;
    const int lane = tid & 31;
    const int g    = lane >> 2;
    const int t    = lane & 3;
    const int mbase = (warp >> 1) * 32;
    const int nbase = (warp & 1) * 64;

    const __half* Arow = A  + (size_t)(by * 128 + (tid >> 1)) * K + (tid & 1) * 32;
    const __half* Brow = BT + (size_t)(bx * 128 + (tid >> 1)) * K + (tid & 1) * 32;
    const int ab_off = (tid >> 1) * GP + (tid & 1) * 16;

    const int iters = K / 64;

    auto issue = [&](int it) {
        uint32_t* as = gsm + (it % 3) * GSTG;
        const __half* asrc = Arow + it * 64;
        #pragma unroll
        for (int i = 0; i < 4; i++)
            cp_async16(&as[ab_off + 4 * i], asrc + 8 * i);
        uint32_t* bs = as + GS_A;
        const __half* bsrc = Brow + it * 64;
        #pragma unroll
        for (int i = 0; i < 4; i++)
            cp_async16(&bs[ab_off + 4 * i], bsrc + 8 * i);
        asm volatile("cp.async.commit_group;\n" ::: "memory");
    };

    float acc[2][8][4];
    #pragma unroll
    for (int i = 0; i < 2; i++)
        #pragma unroll
        for (int j = 0; j < 8; j++)
            #pragma unroll
            for (int r = 0; r < 4; r++) acc[i][j][r] = 0.f;

    issue(0);
    if (iters > 1) issue(1);

    for (int it = 0; it < iters; it++) {
        if (it + 1 < iters)
            asm volatile("cp.async.wait_group 1;\n" ::: "memory");
        else
            asm volatile("cp.async.wait_group 0;\n" ::: "memory");
        __syncthreads();   // stage it landed AND all warps done reading it-1

        if (it + 2 < iters) issue(it + 2);   // overwrites buffer (it-1)%3

        const uint32_t* as = gsm + (it % 3) * GSTG;
        const uint32_t* bs = as + GS_A;

        #pragma unroll
        for (int kc = 0; kc < 4; kc++) {
            uint32_t af[2][4];
            #pragma unroll
            for (int mf = 0; mf < 2; mf++) {
                const int m0 = mbase + mf * 16 + g;
                af[mf][0] = as[(m0    ) * GP + 8 * kc + t];
                af[mf][1] = as[(m0 + 8) * GP + 8 * kc + t];
                af[mf][2] = as[(m0    ) * GP + 8 * kc + t + 4];
                af[mf][3] = as[(m0 + 8) * GP + 8 * kc + t + 4];
            }
            uint32_t bf[8][2];
            #pragma unroll
            for (int nf = 0; nf < 8; nf++) {
                const int n0 = nbase + nf * 8 + g;
                bf[nf][0] = bs[n0 * GP + 8 * kc + t];
                bf[nf][1] = bs[n0 * GP + 8 * kc + t + 4];
            }
            #pragma unroll
            for (int mf = 0; mf < 2; mf++)
                #pragma unroll
                for (int nf = 0; nf < 8; nf++)
                    mma_f16(acc[mf][nf], af[mf][0], af[mf][1], af[mf][2],
                            af[mf][3], bf[nf][0], bf[nf][1]);
        }
    }

    #pragma unroll
    for (int mf = 0; mf < 2; mf++) {
        const int row = by * 128 + mbase + mf * 16 + g;
        #pragma unroll
        for (int nf = 0; nf < 8; nf++) {
            const int col = bx * 128 + nbase + nf * 8 + 2 * t;
            if (half_out) {
                __half* Ch = (__half*)C;
                *(uint32_t*)(Ch + (size_t)row * N + col) =
                    pack_half2(acc[mf][nf][0], acc[mf][nf][1]);
                *(uint32_t*)(Ch + (size_t)(row + 8) * N + col) =
                    pack_half2(acc[mf][nf][2], acc[mf][nf][3]);
            } else {
                float* Cf = (float*)C;
                *(float2*)(Cf + (size_t)row * N + col) =
                    make_float2(acc[mf][nf][0], acc[mf][nf][1]);
                *(float2*)(Cf + (size_t)(row + 8) * N + col) =
                    make_float2(acc[mf][nf][2], acc[mf][nf][3]);
            }
        }
    }
}

__global__ __launch_bounds__(256, 2) void gemm_qkv(
    const __half* __restrict__ x,
    const __half* __restrict__ WqT, const __half* __restrict__ WkT,
    const __half* __restrict__ WvT,
    __half* __restrict__ Qp, __half* __restrict__ Kp, __half* __restrict__ Vp)
{
    extern __shared__ uint32_t gsm[];
    const int bx = blockIdx.x;
    if (bx < 16)      gemm_core_h(x, WqT, Qp, true, ND,   ND, bx,      blockIdx.y, gsm);
    else if (bx < 20) gemm_core_h(x, WkT, Kp, true, NDKV, ND, bx - 16, blockIdx.y, gsm);
    else              gemm_core_h(x, WvT, Vp, true, NDKV, ND, bx - 20, blockIdx.y, gsm);
}

__global__ __launch_bounds__(256, 2) void gemm_out(
    const __half* __restrict__ A, const __half* __restrict__ BT,
    float* __restrict__ C)
{
    extern __shared__ uint32_t gsm[];
    gemm_core_h(A, BT, C, false, ND, ND, blockIdx.x, blockIdx.y, gsm);
}

// ---------------------------------------------------------------------------
// fp16 MMA flash attention (exact R10 version — proven 273.7us).
// Br=256 (8 warps x 2 m-frags), Bc=64, dh=64. K 3-buf cp.async, V 2-buf
// LDG + transposed STS, fp32 exp2 softmax, pack_half2 P->A-frags.
// ---------------------------------------------------------------------------
#define FP       36
#define KBUF     (64 * FP)
#define FA_SMEM  (5 * KBUF * (int)sizeof(uint32_t))   // 46080 B
#define NTILES   (NT / 64)

__global__ __launch_bounds__(256) void flash_h(
    const __half* __restrict__ Q, const __half* __restrict__ K,
    const __half* __restrict__ V, __half* __restrict__ O)
{
    extern __shared__ uint32_t sm[];

    const int tid  = threadIdx.x;
    const int warp = tid >> 5;
    const int lane = tid & 31;
    const int g    = lane >> 2;
    const int tq   = lane & 3;
    const int bh   = blockIdx.y;
    const int b    = bh >> 5;
    const int h    = bh & 31;
    const int hkv  = h >> 2;
    const int q0   = blockIdx.x * 256;

    const int krow = tid >> 2;
    const int kq   = tid & 3;
    const int vt2  = tid & 31;
    const int vdb  = (tid >> 5) * 8;

    {
        const __half* s0 = K + (size_t)(b * NT + krow) * NDKV + hkv * NDH + kq * 16;
        cp_async16(&sm[krow * FP + kq * 8],     s0);
        cp_async16(&sm[krow * FP + kq * 8 + 4], s0 + 8);
        asm volatile("cp.async.commit_group;\n" ::: "memory");
        const __half* s1 = s0 + (size_t)64 * NDKV;
        cp_async16(&sm[KBUF + krow * FP + kq * 8],     s1);
        cp_async16(&sm[KBUF + krow * FP + kq * 8 + 4], s1 + 8);
        asm volatile("cp.async.commit_group;\n" ::: "memory");
    }
    uint4 v0, v1;
    {
        const __half* src = V + (size_t)(b * NT + 2 * vt2) * NDKV + hkv * NDH + vdb;
        v0 = *(const uint4*)(src);
        v1 = *(const uint4*)(src + NDKV);
    }
    const float QSC = 0.18033688011112042f;   // 0.125 * log2(e)
    const __half2 qsc2 = __float2half2_rn(QSC);
    uint32_t qa[2][4][4];
    {
        #pragma unroll
        for (int f = 0; f < 2; f++) {
            const size_t r0 = (size_t)(b * NT + q0 + warp * 32 + 16 * f + g);
            const uint32_t* p0 = (const uint32_t*)(Q + r0 * ND + h * NDH);
            const uint32_t* p1 = (const uint32_t*)(Q + (r0 + 8) * ND + h * NDH);
            #pragma unroll
            for (int kc = 0; kc < 4; kc++) {
                qa[f][kc][0] = p0[8 * kc + tq];
                qa[f][kc][1] = p1[8 * kc + tq];
                qa[f][kc][2] = p0[8 * kc + tq + 4];
                qa[f][kc][3] = p1[8 * kc + tq + 4];
                #pragma unroll
                for (int r = 0; r < 4; r++) {
                    __half2 hv = __hmul2(*(const __half2*)&qa[f][kc][r], qsc2);
                    qa[f][kc][r] = *(const uint32_t*)&hv;
                }
            }
        }
    }
    {
        uint32_t* dst = sm + 3 * KBUF;
        const __half* h0 = (const __half*)&v0;
        const __half* h1 = (const __half*)&v1;
        #pragma unroll
        for (int i = 0; i < 8; i++) {
            __half2 p = __halves2half2(h0[i], h1[i]);
            dst[(vdb + i) * FP + vt2] = *(const uint32_t*)&p;
        }
    }
    {
        const __half* src = V + (size_t)(b * NT + 64 + 2 * vt2) * NDKV + hkv * NDH + vdb;
        v0 = *(const uint4*)(src);
        v1 = *(const uint4*)(src + NDKV);
    }
    __syncthreads();

    float mrow[2][2], lrow[2][2];
    #pragma unroll
    for (int f = 0; f < 2; f++) { mrow[f][0] = mrow[f][1] = -1e30f;
                                  lrow[f][0] = lrow[f][1] = 0.f; }
    float acc_o[2][8][4];
    #pragma unroll
    for (int f = 0; f < 2; f++)
        #pragma unroll
        for (int j = 0; j < 8; j++)
            #pragma unroll
            for (int r = 0; r < 4; r++) acc_o[f][j][r] = 0.f;

    const unsigned fm = 0xffffffffu;

    for (int kb = 0; kb < NTILES; kb++) {
        const int vb   = kb & 1;
        const bool pre1 = kb + 1 < NTILES;
        const bool pre2 = kb + 2 < NTILES;

        if (pre1) asm volatile("cp.async.wait_group 1;\n" ::: "memory");
        else      asm volatile("cp.async.wait_group 0;\n" ::: "memory");
        __syncthreads();

        if (pre2) {
            uint32_t* kdst = sm + ((kb + 2) % 3) * KBUF;
            const __half* src = K + (size_t)(b * NT + (kb + 2) * 64 + krow) * NDKV
                                + hkv * NDH + kq * 16;
            cp_async16(&kdst[krow * FP + kq * 8],     src);
            cp_async16(&kdst[krow * FP + kq * 8 + 4], src + 8);
            asm volatile("cp.async.commit_group;\n" ::: "memory");
        }

        float s[2][8][4];
        #pragma unroll
        for (int f = 0; f < 2; f++)
            #pragma unroll
            for (int j = 0; j < 8; j++)
                #pragma unroll
                for (int r = 0; r < 4; r++) s[f][j][r] = 0.f;
        {
            const uint32_t* kp = sm + (kb % 3) * KBUF;
            #pragma unroll
            for (int kc = 0; kc < 4; kc++)
                #pragma unroll
                for (int j = 0; j < 8; j++) {
                    const uint32_t b0 = kp[(8 * j + g) * FP + 8 * kc + tq];
                    const uint32_t b1 = kp[(8 * j + g) * FP + 8 * kc + tq + 4];
                    mma_f16(s[0][j], qa[0][kc][0], qa[0][kc][1], qa[0][kc][2],
                            qa[0][kc][3], b0, b1);
                    mma_f16(s[1][j], qa[1][kc][0], qa[1][kc][1], qa[1][kc][2],
                            qa[1][kc][3], b0, b1);
                }
        }

        if (pre1) {
            uint32_t* dst = sm + (3 + (vb ^ 1)) * KBUF;
            const __half* h0 = (const __half*)&v0;
            const __half* h1 = (const __half*)&v1;
            #pragma unroll
            for (int i = 0; i < 8; i++) {
                __half2 p = __halves2half2(h0[i], h1[i]);
                dst[(vdb + i) * FP + vt2] = *(const uint32_t*)&p;
            }
        }
        if (pre2) {
            const __half* src = V + (size_t)(b * NT + (kb + 2) * 64 + 2 * vt2) * NDKV
                                + hkv * NDH + vdb;
            v0 = *(const uint4*)(src);
            v1 = *(const uint4*)(src + NDKV);
        }

        #pragma unroll
        for (int f = 0; f < 2; f++) {
            float mt0 = -1e30f, mt1 = -1e30f;
            #pragma unroll
            for (int j = 0; j < 8; j++) {
                mt0 = fmaxf(mt0, fmaxf(s[f][j][0], s[f][j][1]));
                mt1 = fmaxf(mt1, fmaxf(s[f][j][2], s[f][j][3]));
            }
            mt0 = fmaxf(mt0, __shfl_xor_sync(fm, mt0, 1));
            mt0 = fmaxf(mt0, __shfl_xor_sync(fm, mt0, 2));
            mt1 = fmaxf(mt1, __shfl_xor_sync(fm, mt1, 1));
            mt1 = fmaxf(mt1, __shfl_xor_sync(fm, mt1, 2));
            const float mn0 = fmaxf(mrow[f][0], mt0);
            const float mn1 = fmaxf(mrow[f][1], mt1);
            const float al0 = exp2f(mrow[f][0] - mn0);
            const float al1 = exp2f(mrow[f][1] - mn1);
            mrow[f][0] = mn0; mrow[f][1] = mn1;
            float rs0 = 0.f, rs1 = 0.f;
            #pragma unroll
            for (int j = 0; j < 8; j++) {
                s[f][j][0] = exp2f(s[f][j][0] - mn0); rs0 += s[f][j][0];
                s[f][j][1] = exp2f(s[f][j][1] - mn0); rs0 += s[f][j][1];
                s[f][j][2] = exp2f(s[f][j][2] - mn1); rs1 += s[f][j][2];
                s[f][j][3] = exp2f(s[f][j][3] - mn1); rs1 += s[f][j][3];
            }
            rs0 += __shfl_xor_sync(fm, rs0, 1);
            rs0 += __shfl_xor_sync(fm, rs0, 2);
            rs1 += __shfl_xor_sync(fm, rs1, 1);
            rs1 += __shfl_xor_sync(fm, rs1, 2);
            lrow[f][0] = lrow[f][0] * al0 + rs0;
            lrow[f][1] = lrow[f][1] * al1 + rs1;
            #pragma unroll
            for (int j = 0; j < 8; j++) {
                acc_o[f][j][0] *= al0; acc_o[f][j][1] *= al0;
                acc_o[f][j][2] *= al1; acc_o[f][j][3] *= al1;
            }
        }

        {
            const uint32_t* vt = sm + (3 + vb) * KBUF;
            #pragma unroll
            for (int kc = 0; kc < 4; kc++) {
                uint32_t pa[2][4];
                #pragma unroll
                for (int f = 0; f < 2; f++) {
                    pa[f][0] = pack_half2(s[f][2 * kc][0],     s[f][2 * kc][1]);
                    pa[f][1] = pack_half2(s[f][2 * kc][2],     s[f][2 * kc][3]);
                    pa[f][2] = pack_half2(s[f][2 * kc + 1][0], s[f][2 * kc + 1][1]);
                    pa[f][3] = pack_half2(s[f][2 * kc + 1][2], s[f][2 * kc + 1][3]);
                }
                #pragma unroll
                for (int jd = 0; jd < 8; jd++) {
                    const uint32_t b0 = vt[(8 * jd + g) * FP + 8 * kc + tq];
                    const uint32_t b1 = vt[(8 * jd + g) * FP + 8 * kc + tq + 4];
                    mma_f16(acc_o[0][jd], pa[0][0], pa[0][1], pa[0][2], pa[0][3], b0, b1);
                    mma_f16(acc_o[1][jd], pa[1][0], pa[1][1], pa[1][2], pa[1][3], b0, b1);
                }
            }
        }
    }

    #pragma unroll
    for (int f = 0; f < 2; f++) {
        const float inv0 = 1.0f / lrow[f][0];
        const float inv1 = 1.0f / lrow[f][1];
        const size_t r0 = (size_t)(b * NT + q0 + warp * 32 + 16 * f + g);
        __half* o0 = O + r0 * ND + h * NDH;
        __half* o1 = o0 + (size_t)8 * ND;
        #pragma unroll
        for (int jd = 0; jd < 8; jd++) {
            *(uint32_t*)(o0 + 8 * jd + 2 * tq) =
                pack_half2(acc_o[f][jd][0] * inv0, acc_o[f][jd][1] * inv0);
            *(uint32_t*)(o1 + 8 * jd + 2 * tq) =
                pack_half2(acc_o[f][jd][2] * inv1, acc_o[f][jd][3] * inv1);
        }
    }
}

// ---------------------------------------------------------------------------
extern "C" void kernel_launch(void* const* d_in, const int* in_sizes, int n_in,
                              void* d_out, int out_size)
{
    const float* x  = (const float*)d_in[0];
    const float* Wq = (const float*)d_in[1];
    const float* Wk = (const float*)d_in[2];
    const float* Wv = (const float*)d_in[3];
    const float* Wo = (const float*)d_in[4];
    float* out = (float*)d_out;

    __half *Qh, *Kh, *Vh, *Ah, *Xh, *WqT, *WkT, *WvT, *WoT;
    cudaGetSymbolAddress((void**)&Qh,  g_Qh);
    cudaGetSymbolAddress((void**)&Kh,  g_Kh);
    cudaGetSymbolAddress((void**)&Vh,  g_Vh);
    cudaGetSymbolAddress((void**)&Ah,  g_Ah);
    cudaGetSymbolAddress((void**)&Xh,  g_Xh);
    cudaGetSymbolAddress((void**)&WqT, g_WqT);
    cudaGetSymbolAddress((void**)&WkT, g_WkT);
    cudaGetSymbolAddress((void**)&WvT, g_WvT);
    cudaGetSymbolAddress((void**)&WoT, g_WoT);

    cudaFuncSetAttribute(flash_h,
                         cudaFuncAttributeMaxDynamicSharedMemorySize, FA_SMEM);
    cudaFuncSetAttribute(gemm_qkv,
                         cudaFuncAttributeMaxDynamicSharedMemorySize, G_SMEM);
    cudaFuncSetAttribute(gemm_out,
                         cudaFuncAttributeMaxDynamicSharedMemorySize, G_SMEM);

    const int nX = NTOK * ND / 4;
    cvt_half<<<(nX + 255) / 256, 256>>>(x, Xh, nX);
    transpose4<<<dim3(ND / 32, ND / 32, 4), 256>>>(Wq, Wk, Wv, Wo,
                                                   WqT, WkT, WvT, WoT);

    gemm_qkv<<<dim3(24, 32), 256, G_SMEM>>>(Xh, WqT, WkT, WvT, Qh, Kh, Vh);
    flash_h<<<dim3(NT / 256, NB * NHQ), 256, FA_SMEM>>>(Qh, Kh, Vh, Ah);
    gemm_out<<<dim3(16, 32), 256, G_SMEM>>>(Ah, WoT, out);
}

// round 16
// speedup vs baseline: 1.1125x; 1.1125x over previous
#include <cuda_runtime.h>
#include <cuda_fp16.h>
#include <cstdint>

#define NB   2
#define NT   2048
#define ND   2048
#define NHQ  32
#define NHKV 8
#define NDH  64
#define NTOK (NB*NT)      // 4096
#define NDKV (NHKV*NDH)   // 512

// fp16 scratch (device globals: allocation-free per harness rules)
__device__ __half g_Qh[(size_t)NTOK * ND];     // 16 MB
__device__ __half g_Kh[(size_t)NTOK * NDKV];   // 4 MB
__device__ __half g_Vh[(size_t)NTOK * NDKV];   // 4 MB
__device__ __half g_Ah[(size_t)NTOK * ND];     // 16 MB
__device__ __half g_Xh[(size_t)NTOK * ND];     // 16 MB
__device__ __half g_WqT[(size_t)ND * ND];      // 8 MB  [N][K]
__device__ __half g_WkT[(size_t)NDKV * ND];    // 2 MB
__device__ __half g_WvT[(size_t)NDKV * ND];    // 2 MB
__device__ __half g_WoT[(size_t)ND * ND];      // 8 MB

// ---------------------------------------------------------------------------
__device__ __forceinline__ void mma_f16(float* c, uint32_t a0, uint32_t a1,
                                        uint32_t a2, uint32_t a3,
                                        uint32_t b0, uint32_t b1) {
    asm volatile(
        "mma.sync.aligned.m16n8k16.row.col.f32.f16.f16.f32 "
        "{%0,%1,%2,%3}, {%4,%5,%6,%7}, {%8,%9}, {%0,%1,%2,%3};"
        : "+f"(c[0]), "+f"(c[1]), "+f"(c[2]), "+f"(c[3])
        : "r"(a0), "r"(a1), "r"(a2), "r"(a3), "r"(b0), "r"(b1));
}

__device__ __forceinline__ void cp_async16(void* smem_ptr, const void* gptr) {
    unsigned saddr = (unsigned)__cvta_generic_to_shared(smem_ptr);
    asm volatile("cp.async.cg.shared.global [%0], [%1], 16;\n"
                 :: "r"(saddr), "l"(gptr));
}

__device__ __forceinline__ uint32_t pack_half2(float lo, float hi) {
    uint32_t r;
    asm("cvt.rn.f16x2.f32 %0, %2, %1;" : "=r"(r) : "f"(lo), "f"(hi));
    return r;
}

// ---------------------------------------------------------------------------
// prep kernels
// ---------------------------------------------------------------------------
__global__ __launch_bounds__(256) void cvt_half(
    const float* __restrict__ in, __half* __restrict__ out, int n4)
{
    int i = blockIdx.x * blockDim.x + threadIdx.x;
    if (i < n4) {
        float4 v = ((const float4*)in)[i];
        __half2* o = (__half2*)(out + 4 * (size_t)i);
        o[0] = __floats2half2_rn(v.x, v.y);
        o[1] = __floats2half2_rn(v.z, v.w);
    }
}

// fused transpose of all 4 weights: z selects matrix. fp32 [R][C] -> fp16 [C][R]
__global__ __launch_bounds__(256) void transpose4(
    const float* __restrict__ Wq, const float* __restrict__ Wk,
    const float* __restrict__ Wv, const float* __restrict__ Wo,
    __half* __restrict__ WqT, __half* __restrict__ WkT,
    __half* __restrict__ WvT, __half* __restrict__ WoT)
{
    const int z = blockIdx.z;
    const float* in;
    __half* out;
    int C;
    if (z == 0)      { in = Wq; out = WqT; C = ND; }
    else if (z == 1) { in = Wk; out = WkT; C = NDKV; }
    else if (z == 2) { in = Wv; out = WvT; C = NDKV; }
    else             { in = Wo; out = WoT; C = ND; }
    const int c0 = blockIdx.x * 32;
    if (c0 >= C) return;
    const int R = ND;
    const int r0 = blockIdx.y * 32;

    __shared__ float t[32][33];
    const int tx = threadIdx.x & 31;
    const int ty = threadIdx.x >> 5;
    #pragma unroll
    for (int i = 0; i < 32; i += 8)
        t[ty + i][tx] = in[(size_t)(r0 + ty + i) * C + c0 + tx];
    __syncthreads();
    #pragma unroll
    for (int i = 0; i < 32; i += 8)
        out[(size_t)(c0 + ty + i) * R + r0 + tx] = __float2half_rn(t[tx][ty + i]);
}

// ---------------------------------------------------------------------------
// fp16 GEMM: block 128x128, BK=64, warp tile 32x64, 3-stage cp.async ring,
// 2 CTAs/SM. A fp16 [M][K], BT fp16 [N][K].
// Smem: 32 u32 per row, XOR swizzle col' = col ^ ((row&7)<<2) at 16B grain.
// All fragment LDS patterns hit 32 distinct banks; cp.async16 stays aligned.
// Stage = 32 KB, 3 stages = 96 KB/CTA -> 2 CTAs co-resident.
// ---------------------------------------------------------------------------
#define GS_A   (128 * 32)               // 4096 u32
#define GS_B   (128 * 32)
#define GSTG   (GS_A + GS_B)            // 8192 u32
#define G_SMEM (3 * GSTG * (int)sizeof(uint32_t))   // 98304 B
#define GSW(row, col) ((row) * 32 + ((col) ^ (((row) & 7) << 2)))

__device__ __forceinline__ void gemm_core_h(
    const __half* __restrict__ A, const __half* __restrict__ BT,
    void* __restrict__ C, bool half_out, int N, int K, int bx, int by,
    uint32_t* gsm)
{
    const int tid  = threadIdx.x;
    const int warp = tid >> 5;
    const int lane = tid & 31;
    const int g    = lane >> 2;
    const int t    = lane & 3;
    const int mbase = (warp >> 1) * 32;
    const int nbase = (warp & 1) * 64;

    const int ldrow = tid >> 1;           // 0..127
    const int ldc0  = (tid & 1) * 16;     // 0 or 16 (u32 col)
    const __half* Arow = A  + (size_t)(by * 128 + ldrow) * K + ldc0 * 2;
    const __half* Brow = BT + (size_t)(bx * 128 + ldrow) * K + ldc0 * 2;

    const int iters = K / 64;

    auto issue = [&](int it) {
        uint32_t* as = gsm + (it % 3) * GSTG;
        uint32_t* bs = as + GS_A;
        const __half* asrc = Arow + it * 64;
        const __half* bsrc = Brow + it * 64;
        #pragma unroll
        for (int i = 0; i < 4; i++) {
            const int sw = GSW(ldrow, ldc0 + 4 * i);
            cp_async16(&as[sw], asrc + 8 * i);
            cp_async16(&bs[sw], bsrc + 8 * i);
        }
        asm volatile("cp.async.commit_group;\n" ::: "memory");
    };

    float acc[2][8][4];
    #pragma unroll
    for (int i = 0; i < 2; i++)
        #pragma unroll
        for (int j = 0; j < 8; j++)
            #pragma unroll
            for (int r = 0; r < 4; r++) acc[i][j][r] = 0.f;

    issue(0);
    if (iters > 1) issue(1);

    for (int it = 0; it < iters; it++) {
        if (it + 1 < iters)
            asm volatile("cp.async.wait_group 1;\n" ::: "memory");
        else
            asm volatile("cp.async.wait_group 0;\n" ::: "memory");
        __syncthreads();   // stage it landed AND all warps done reading it-1

        if (it + 2 < iters) issue(it + 2);   // overwrites buffer (it-1)%3

        const uint32_t* as = gsm + (it % 3) * GSTG;
        const uint32_t* bs = as + GS_A;

        #pragma unroll
        for (int kc = 0; kc < 4; kc++) {
            uint32_t af[2][4];
            #pragma unroll
            for (int mf = 0; mf < 2; mf++) {
                const int m0 = mbase + mf * 16 + g;
                af[mf][0] = as[GSW(m0,     8 * kc + t)];
                af[mf][1] = as[GSW(m0 + 8, 8 * kc + t)];
                af[mf][2] = as[GSW(m0,     8 * kc + t + 4)];
                af[mf][3] = as[GSW(m0 + 8, 8 * kc + t + 4)];
            }
            uint32_t bf[8][2];
            #pragma unroll
            for (int nf = 0; nf < 8; nf++) {
                const int n0 = nbase + nf * 8 + g;
                bf[nf][0] = bs[GSW(n0, 8 * kc + t)];
                bf[nf][1] = bs[GSW(n0, 8 * kc + t + 4)];
            }
            #pragma unroll
            for (int mf = 0; mf < 2; mf++)
                #pragma unroll
                for (int nf = 0; nf < 8; nf++)
                    mma_f16(acc[mf][nf], af[mf][0], af[mf][1], af[mf][2],
                            af[mf][3], bf[nf][0], bf[nf][1]);
        }
    }

    #pragma unroll
    for (int mf = 0; mf < 2; mf++) {
        const int row = by * 128 + mbase + mf * 16 + g;
        #pragma unroll
        for (int nf = 0; nf < 8; nf++) {
            const int col = bx * 128 + nbase + nf * 8 + 2 * t;
            if (half_out) {
                __half* Ch = (__half*)C;
                *(uint32_t*)(Ch + (size_t)row * N + col) =
                    pack_half2(acc[mf][nf][0], acc[mf][nf][1]);
                *(uint32_t*)(Ch + (size_t)(row + 8) * N + col) =
                    pack_half2(acc[mf][nf][2], acc[mf][nf][3]);
            } else {
                float* Cf = (float*)C;
                *(float2*)(Cf + (size_t)row * N + col) =
                    make_float2(acc[mf][nf][0], acc[mf][nf][1]);
                *(float2*)(Cf + (size_t)(row + 8) * N + col) =
                    make_float2(acc[mf][nf][2], acc[mf][nf][3]);
            }
        }
    }
}

__global__ __launch_bounds__(256, 2) void gemm_qkv(
    const __half* __restrict__ x,
    const __half* __restrict__ WqT, const __half* __restrict__ WkT,
    const __half* __restrict__ WvT,
    __half* __restrict__ Qp, __half* __restrict__ Kp, __half* __restrict__ Vp)
{
    extern __shared__ uint32_t gsm[];
    const int bx = blockIdx.x;
    if (bx < 16)      gemm_core_h(x, WqT, Qp, true, ND,   ND, bx,      blockIdx.y, gsm);
    else if (bx < 20) gemm_core_h(x, WkT, Kp, true, NDKV, ND, bx - 16, blockIdx.y, gsm);
    else              gemm_core_h(x, WvT, Vp, true, NDKV, ND, bx - 20, blockIdx.y, gsm);
}

__global__ __launch_bounds__(256, 2) void gemm_out(
    const __half* __restrict__ A, const __half* __restrict__ BT,
    float* __restrict__ C)
{
    extern __shared__ uint32_t gsm[];
    gemm_core_h(A, BT, C, false, ND, ND, blockIdx.x, blockIdx.y, gsm);
}

// ---------------------------------------------------------------------------
// fp16 MMA flash attention (exact R10 version — proven 273.4us x3 runs).
// Br=256 (8 warps x 2 m-frags), Bc=64, dh=64. K 3-buf cp.async, V 2-buf
// LDG + transposed STS, fp32 exp2 softmax, pack_half2 P->A-frags.
// ---------------------------------------------------------------------------
#define FP       36
#define KBUF     (64 * FP)
#define FA_SMEM  (5 * KBUF * (int)sizeof(uint32_t))   // 46080 B
#define NTILES   (NT / 64)

__global__ __launch_bounds__(256) void flash_h(
    const __half* __restrict__ Q, const __half* __restrict__ K,
    const __half* __restrict__ V, __half* __restrict__ O)
{
    extern __shared__ uint32_t sm[];

    const int tid  = threadIdx.x;
    const int warp = tid >> 5;
    const int lane = tid & 31;
    const int g    = lane >> 2;
    const int tq   = lane & 3;
    const int bh   = blockIdx.y;
    const int b    = bh >> 5;
    const int h    = bh & 31;
    const int hkv  = h >> 2;
    const int q0   = blockIdx.x * 256;

    const int krow = tid >> 2;
    const int kq   = tid & 3;
    const int vt2  = tid & 31;
    const int vdb  = (tid >> 5) * 8;

    {
        const __half* s0 = K + (size_t)(b * NT + krow) * NDKV + hkv * NDH + kq * 16;
        cp_async16(&sm[krow * FP + kq * 8],     s0);
        cp_async16(&sm[krow * FP + kq * 8 + 4], s0 + 8);
        asm volatile("cp.async.commit_group;\n" ::: "memory");
        const __half* s1 = s0 + (size_t)64 * NDKV;
        cp_async16(&sm[KBUF + krow * FP + kq * 8],     s1);
        cp_async16(&sm[KBUF + krow * FP + kq * 8 + 4], s1 + 8);
        asm volatile("cp.async.commit_group;\n" ::: "memory");
    }
    uint4 v0, v1;
    {
        const __half* src = V + (size_t)(b * NT + 2 * vt2) * NDKV + hkv * NDH + vdb;
        v0 = *(const uint4*)(src);
        v1 = *(const uint4*)(src + NDKV);
    }
    const float QSC = 0.18033688011112042f;   // 0.125 * log2(e)
    const __half2 qsc2 = __float2half2_rn(QSC);
    uint32_t qa[2][4][4];
    {
        #pragma unroll
        for (int f = 0; f < 2; f++) {
            const size_t r0 = (size_t)(b * NT + q0 + warp * 32 + 16 * f + g);
            const uint32_t* p0 = (const uint32_t*)(Q + r0 * ND + h * NDH);
            const uint32_t* p1 = (const uint32_t*)(Q + (r0 + 8) * ND + h * NDH);
            #pragma unroll
            for (int kc = 0; kc < 4; kc++) {
                qa[f][kc][0] = p0[8 * kc + tq];
                qa[f][kc][1] = p1[8 * kc + tq];
                qa[f][kc][2] = p0[8 * kc + tq + 4];
                qa[f][kc][3] = p1[8 * kc + tq + 4];
                #pragma unroll
                for (int r = 0; r < 4; r++) {
                    __half2 hv = __hmul2(*(const __half2*)&qa[f][kc][r], qsc2);
                    qa[f][kc][r] = *(const uint32_t*)&hv;
                }
            }
        }
    }
    {
        uint32_t* dst = sm + 3 * KBUF;
        const __half* h0 = (const __half*)&v0;
        const __half* h1 = (const __half*)&v1;
        #pragma unroll
        for (int i = 0; i < 8; i++) {
            __half2 p = __halves2half2(h0[i], h1[i]);
            dst[(vdb + i) * FP + vt2] = *(const uint32_t*)&p;
        }
    }
    {
        const __half* src = V + (size_t)(b * NT + 64 + 2 * vt2) * NDKV + hkv * NDH + vdb;
        v0 = *(const uint4*)(src);
        v1 = *(const uint4*)(src + NDKV);
    }
    __syncthreads();

    float mrow[2][2], lrow[2][2];
    #pragma unroll
    for (int f = 0; f < 2; f++) { mrow[f][0] = mrow[f][1] = -1e30f;
                                  lrow[f][0] = lrow[f][1] = 0.f; }
    float acc_o[2][8][4];
    #pragma unroll
    for (int f = 0; f < 2; f++)
        #pragma unroll
        for (int j = 0; j < 8; j++)
            #pragma unroll
            for (int r = 0; r < 4; r++) acc_o[f][j][r] = 0.f;

    const unsigned fm = 0xffffffffu;

    for (int kb = 0; kb < NTILES; kb++) {
        const int vb   = kb & 1;
        const bool pre1 = kb + 1 < NTILES;
        const bool pre2 = kb + 2 < NTILES;

        if (pre1) asm volatile("cp.async.wait_group 1;\n" ::: "memory");
        else      asm volatile("cp.async.wait_group 0;\n" ::: "memory");
        __syncthreads();

        if (pre2) {
            uint32_t* kdst = sm + ((kb + 2) % 3) * KBUF;
            const __half* src = K + (size_t)(b * NT + (kb + 2) * 64 + krow) * NDKV
                                + hkv * NDH + kq * 16;
            cp_async16(&kdst[krow * FP + kq * 8],     src);
            cp_async16(&kdst[krow * FP + kq * 8 + 4], src + 8);
            asm volatile("cp.async.commit_group;\n" ::: "memory");
        }

        float s[2][8][4];
        #pragma unroll
        for (int f = 0; f < 2; f++)
            #pragma unroll
            for (int j = 0; j < 8; j++)
                #pragma unroll
                for (int r = 0; r < 4; r++) s[f][j][r] = 0.f;
        {
            const uint32_t* kp = sm + (kb % 3) * KBUF;
            #pragma unroll
            for (int kc = 0; kc < 4; kc++)
                #pragma unroll
                for (int j = 0; j < 8; j++) {
                    const uint32_t b0 = kp[(8 * j + g) * FP + 8 * kc + tq];
                    const uint32_t b1 = kp[(8 * j + g) * FP + 8 * kc + tq + 4];
                    mma_f16(s[0][j], qa[0][kc][0], qa[0][kc][1], qa[0][kc][2],
                            qa[0][kc][3], b0, b1);
                    mma_f16(s[1][j], qa[1][kc][0], qa[1][kc][1], qa[1][kc][2],
                            qa[1][kc][3], b0, b1);
                }
        }

        if (pre1) {
            uint32_t* dst = sm + (3 + (vb ^ 1)) * KBUF;
            const __half* h0 = (const __half*)&v0;
            const __half* h1 = (const __half*)&v1;
            #pragma unroll
            for (int i = 0; i < 8; i++) {
                __half2 p = __halves2half2(h0[i], h1[i]);
                dst[(vdb + i) * FP + vt2] = *(const uint32_t*)&p;
            }
        }
        if (pre2) {
            const __half* src = V + (size_t)(b * NT + (kb + 2) * 64 + 2 * vt2) * NDKV
                                + hkv * NDH + vdb;
            v0 = *(const uint4*)(src);
            v1 = *(const uint4*)(src + NDKV);
        }

        #pragma unroll
        for (int f = 0; f < 2; f++) {
            float mt0 = -1e30f, mt1 = -1e30f;
            #pragma unroll
            for (int j = 0; j < 8; j++) {
                mt0 = fmaxf(mt0, fmaxf(s[f][j][0], s[f][j][1]));
                mt1 = fmaxf(mt1, fmaxf(s[f][j][2], s[f][j][3]));
            }
            mt0 = fmaxf(mt0, __shfl_xor_sync(fm, mt0, 1));
            mt0 = fmaxf(mt0, __shfl_xor_sync(fm, mt0, 2));
            mt1 = fmaxf(mt1, __shfl_xor_sync(fm, mt1, 1));
            mt1 = fmaxf(mt1, __shfl_xor_sync(fm, mt1, 2));
            const float mn0 = fmaxf(mrow[f][0], mt0);
            const float mn1 = fmaxf(mrow[f][1], mt1);
            const float al0 = exp2f(mrow[f][0] - mn0);
            const float al1 = exp2f(mrow[f][1] - mn1);
            mrow[f][0] = mn0; mrow[f][1] = mn1;
            float rs0 = 0.f, rs1 = 0.f;
            #pragma unroll
            for (int j = 0; j < 8; j++) {
                s[f][j][0] = exp2f(s[f][j][0] - mn0); rs0 += s[f][j][0];
                s[f][j][1] = exp2f(s[f][j][1] - mn0); rs0 += s[f][j][1];
                s[f][j][2] = exp2f(s[f][j][2] - mn1); rs1 += s[f][j][2];
                s[f][j][3] = exp2f(s[f][j][3] - mn1); rs1 += s[f][j][3];
            }
            rs0 += __shfl_xor_sync(fm, rs0, 1);
            rs0 += __shfl_xor_sync(fm, rs0, 2);
            rs1 += __shfl_xor_sync(fm, rs1, 1);
            rs1 += __shfl_xor_sync(fm, rs1, 2);
            lrow[f][0] = lrow[f][0] * al0 + rs0;
            lrow[f][1] = lrow[f][1] * al1 + rs1;
            #pragma unroll
            for (int j = 0; j < 8; j++) {
                acc_o[f][j][0] *= al0; acc_o[f][j][1] *= al0;
                acc_o[f][j][2] *= al1; acc_o[f][j][3] *= al1;
            }
        }

        {
            const uint32_t* vt = sm + (3 + vb) * KBUF;
            #pragma unroll
            for (int kc = 0; kc < 4; kc++) {
                uint32_t pa[2][4];
                #pragma unroll
                for (int f = 0; f < 2; f++) {
                    pa[f][0] = pack_half2(s[f][2 * kc][0],     s[f][2 * kc][1]);
                    pa[f][1] = pack_half2(s[f][2 * kc][2],     s[f][2 * kc][3]);
                    pa[f][2] = pack_half2(s[f][2 * kc + 1][0], s[f][2 * kc + 1][1]);
                    pa[f][3] = pack_half2(s[f][2 * kc + 1][2], s[f][2 * kc + 1][3]);
                }
                #pragma unroll
                for (int jd = 0; jd < 8; jd++) {
                    const uint32_t b0 = vt[(8 * jd + g) * FP + 8 * kc + tq];
                    const uint32_t b1 = vt[(8 * jd + g) * FP + 8 * kc + tq + 4];
                    mma_f16(acc_o[0][jd], pa[0][0], pa[0][1], pa[0][2], pa[0][3], b0, b1);
                    mma_f16(acc_o[1][jd], pa[1][0], pa[1][1], pa[1][2], pa[1][3], b0, b1);
                }
            }
        }
    }

    #pragma unroll
    for (int f = 0; f < 2; f++) {
        const float inv0 = 1.0f / lrow[f][0];
        const float inv1 = 1.0f / lrow[f][1];
        const size_t r0 = (size_t)(b * NT + q0 + warp * 32 + 16 * f + g);
        __half* o0 = O + r0 * ND + h * NDH;
        __half* o1 = o0 + (size_t)8 * ND;
        #pragma unroll
        for (int jd = 0; jd < 8; jd++) {
            *(uint32_t*)(o0 + 8 * jd + 2 * tq) =
                pack_half2(acc_o[f][jd][0] * inv0, acc_o[f][jd][1] * inv0);
            *(uint32_t*)(o1 + 8 * jd + 2 * tq) =
                pack_half2(acc_o[f][jd][2] * inv1, acc_o[f][jd][3] * inv1);
        }
    }
}

// ---------------------------------------------------------------------------
extern "C" void kernel_launch(void* const* d_in, const int* in_sizes, int n_in,
                              void* d_out, int out_size)
{
    const float* x  = (const float*)d_in[0];
    const float* Wq = (const float*)d_in[1];
    const float* Wk = (const float*)d_in[2];
    const float* Wv = (const float*)d_in[3];
    const float* Wo = (const float*)d_in[4];
    float* out = (float*)d_out;

    __half *Qh, *Kh, *Vh, *Ah, *Xh, *WqT, *WkT, *WvT, *WoT;
    cudaGetSymbolAddress((void**)&Qh,  g_Qh);
    cudaGetSymbolAddress((void**)&Kh,  g_Kh);
    cudaGetSymbolAddress((void**)&Vh,  g_Vh);
    cudaGetSymbolAddress((void**)&Ah,  g_Ah);
    cudaGetSymbolAddress((void**)&Xh,  g_Xh);
    cudaGetSymbolAddress((void**)&WqT, g_WqT);
    cudaGetSymbolAddress((void**)&WkT, g_WkT);
    cudaGetSymbolAddress((void**)&WvT, g_WvT);
    cudaGetSymbolAddress((void**)&WoT, g_WoT);

    cudaFuncSetAttribute(flash_h,
                         cudaFuncAttributeMaxDynamicSharedMemorySize, FA_SMEM);
    cudaFuncSetAttribute(gemm_qkv,
                         cudaFuncAttributeMaxDynamicSharedMemorySize, G_SMEM);
    cudaFuncSetAttribute(gemm_out,
                         cudaFuncAttributeMaxDynamicSharedMemorySize, G_SMEM);

    const int nX = NTOK * ND / 4;
    cvt_half<<<(nX + 255) / 256, 256>>>(x, Xh, nX);
    transpose4<<<dim3(ND / 32, ND / 32, 4), 256>>>(Wq, Wk, Wv, Wo,
                                                   WqT, WkT, WvT, WoT);

    gemm_qkv<<<dim3(24, 32), 256, G_SMEM>>>(Xh, WqT, WkT, WvT, Qh, Kh, Vh);
    flash_h<<<dim3(NT / 256, NB * NHQ), 256, FA_SMEM>>>(Qh, Kh, Vh, Ah);
    gemm_out<<<dim3(16, 32), 256, G_SMEM>>>(Ah, WoT, out);
}